// round 7
// baseline (speedup 1.0000x reference)
#include <cuda_runtime.h>
#include <cuda_bf16.h>
#include <cstdint>

#define BATCH 64
#define TT 1024
#define DD 512
#define HH 512
#define J4 2048
#define GRID_R 128        // scan grid (<=148 SMs -> co-resident, barrier safe)

// Scratch (static device memory; no runtime allocation)
__device__ float g_xwt[(size_t)TT * 128 * 64 * 16];   // [t][bu][ab][ut][g]  512 MB
__device__ __nv_bfloat16 g_wib_hi[(size_t)J4 * DD];   // [n][k] bf16 hi      2 MB
__device__ __nv_bfloat16 g_wib_lo[(size_t)J4 * DD];   // [n][k] bf16 lo      2 MB
__device__ __nv_bfloat16 g_whB_hi[(size_t)GRID_R * 16 * 512];  // [bu][r][k]  2 MB
__device__ __nv_bfloat16 g_whB_lo[(size_t)GRID_R * 16 * 512];  // [bu][r][k]  2 MB
__device__ __nv_bfloat16 g_hb_hi[2][BATCH * HH];      // h bf16 hi, [b][u]
__device__ __nv_bfloat16 g_hb_lo[2][BATCH * HH];      // h bf16 lo, [b][u]
__device__ unsigned g_arrive[GRID_R * 8];             // padded arrival flags
__device__ unsigned g_rel;

// ---------------------------------------------------------------------------
__device__ __forceinline__ uint32_t smem_u32(const void* p) {
    uint32_t a;
    asm("{ .reg .u64 t; cvta.to.shared.u64 t, %1; cvt.u32.u64 %0, t; }"
        : "=r"(a) : "l"(p));
    return a;
}
#define CP_ASYNC16(dst, src) \
    asm volatile("cp.async.cg.shared.global [%0], [%1], 16;" :: "r"(dst), "l"(src))
#define CP_COMMIT()  asm volatile("cp.async.commit_group;" ::: "memory")
#define CP_WAIT(n)   asm volatile("cp.async.wait_group %0;" :: "n"(n) : "memory")

#define MMA_BF16(d, a0, a1, a2, a3, b0, b1)                                    \
    asm volatile("mma.sync.aligned.m16n8k16.row.col.f32.bf16.bf16.f32 "        \
                 "{%0,%1,%2,%3},{%4,%5,%6,%7},{%8,%9},{%0,%1,%2,%3};"          \
                 : "+f"((d)[0]), "+f"((d)[1]), "+f"((d)[2]), "+f"((d)[3])      \
                 : "r"(a0), "r"(a1), "r"(a2), "r"(a3), "r"(b0), "r"(b1))

__device__ __forceinline__ void st_rel(unsigned* p, unsigned v) {
    asm volatile("st.release.gpu.u32 [%0], %1;" :: "l"(p), "r"(v) : "memory");
}
__device__ __forceinline__ unsigned ld_acq(const unsigned* p) {
    unsigned v;
    asm volatile("ld.acquire.gpu.u32 %0, [%1];" : "=r"(v) : "l"(p) : "memory");
    return v;
}

// ---------------------------------------------------------------------------
__global__ void reset_bar_kernel() {
    if (threadIdx.x < GRID_R * 8) g_arrive[threadIdx.x] = 0u;
    if (threadIdx.x == 0) g_rel = 0u;
}

// Wi[k][n] -> bf16 hi/lo split, transposed [n][k]
__global__ void pack_wi_kernel(const float* __restrict__ Wi) {
    int i = blockIdx.x * 256 + threadIdx.x;
    int k = i & 511;
    int n = i >> 9;
    float w = Wi[(size_t)k * J4 + n];
    __nv_bfloat16 hi = __float2bfloat16(w);
    __nv_bfloat16 lo = __float2bfloat16(w - __bfloat162float(hi));
    g_wib_hi[i] = hi;
    g_wib_lo[i] = lo;
}

// Wh -> per-block B-operand slices: g_whB[bu][r=ut*4+g][k], bf16 hi/lo
__global__ void pack_whB_kernel(const float* __restrict__ Wh) {
    int i  = blockIdx.x * 256 + threadIdx.x;
    int k  = i & 511;
    int r  = (i >> 9) & 15;
    int bu = i >> 13;
    int ut = r >> 2, g = r & 3;
    float w = Wh[(size_t)k * J4 + g * 512 + bu * 4 + ut];
    __nv_bfloat16 hi = __float2bfloat16(w);
    __nv_bfloat16 lo = __float2bfloat16(w - __bfloat162float(hi));
    g_whB_hi[i] = hi;
    g_whB_lo[i] = lo;
}

// ---------------------------------------------------------------------------
// HMMA GEMM for x@Wi (unchanged from R6, proven): 128x128xK512, hi/lo split.
// ---------------------------------------------------------------------------
__device__ __forceinline__ void cvt8(const float* f, uint4& hi, uint4& lo) {
    uint32_t h[4], l[4];
#pragma unroll
    for (int j = 0; j < 4; j++) {
        __nv_bfloat16 a = __float2bfloat16(f[2 * j]);
        __nv_bfloat16 b = __float2bfloat16(f[2 * j + 1]);
        __nv_bfloat16 ra = __float2bfloat16(f[2 * j] - __bfloat162float(a));
        __nv_bfloat16 rb = __float2bfloat16(f[2 * j + 1] - __bfloat162float(b));
        __nv_bfloat162 hv; hv.x = a;  hv.y = b;
        __nv_bfloat162 lv; lv.x = ra; lv.y = rb;
        h[j] = *(uint32_t*)&hv;
        l[j] = *(uint32_t*)&lv;
    }
    hi = make_uint4(h[0], h[1], h[2], h[3]);
    lo = make_uint4(l[0], l[1], l[2], l[3]);
}

#define RSTRIDE 80

__device__ __forceinline__ void st_xwt(int m, int j, float v) {
    int b = m >> 10, trow = m & 1023, u = j & 511, g = j >> 9;
    g_xwt[(size_t)trow * 131072 + (size_t)(u >> 2) * 1024 + b * 16 + (u & 3) * 4 + g] = v;
}

__global__ __launch_bounds__(256) void gemm_hmma_kernel(
    const float* __restrict__ X, const float* __restrict__ bias)
{
    __shared__ __align__(16) char smAH[128 * RSTRIDE];
    __shared__ __align__(16) char smAL[128 * RSTRIDE];
    __shared__ __align__(16) char smBH[128 * RSTRIDE];
    __shared__ __align__(16) char smBL[128 * RSTRIDE];

    const int nBase = blockIdx.x * 128;
    const int mBase = blockIdx.y * 128;
    const int tid = threadIdx.x;
    const int wid = tid >> 5;
    const int lane = tid & 31;
    const int wm = wid >> 2;
    const int wn = wid & 3;
    const int tig = lane & 3;
    const int grp = lane >> 2;
    const int fr = tid >> 1;
    const int fk = (tid & 1) * 16;

    float acc[4][4][4];
#pragma unroll
    for (int mt = 0; mt < 4; mt++)
#pragma unroll
        for (int nt = 0; nt < 4; nt++)
#pragma unroll
            for (int q = 0; q < 4; q++) acc[mt][nt][q] = 0.f;

    for (int ch = 0; ch < 16; ch++) {
        const int k0 = ch * 32;
        const float* xr = X + (size_t)(mBase + fr) * DD + k0 + fk;
        float4 v0 = __ldg((const float4*)xr);
        float4 v1 = __ldg((const float4*)(xr + 4));
        float4 v2 = __ldg((const float4*)(xr + 8));
        float4 v3 = __ldg((const float4*)(xr + 12));
        const uint4* ph = (const uint4*)(g_wib_hi + (size_t)(nBase + fr) * 512 + k0 + fk);
        const uint4* pl = (const uint4*)(g_wib_lo + (size_t)(nBase + fr) * 512 + k0 + fk);
        uint4 bh0 = __ldg(ph), bh1 = __ldg(ph + 1);
        uint4 bl0 = __ldg(pl), bl1 = __ldg(pl + 1);

        __syncthreads();
        {
            float fa[8] = {v0.x, v0.y, v0.z, v0.w, v1.x, v1.y, v1.z, v1.w};
            float fb[8] = {v2.x, v2.y, v2.z, v2.w, v3.x, v3.y, v3.z, v3.w};
            uint4 h0, l0, h1, l1;
            cvt8(fa, h0, l0);
            cvt8(fb, h1, l1);
            int off = fr * RSTRIDE + fk * 2;
            *(uint4*)(smAH + off)      = h0;
            *(uint4*)(smAH + off + 16) = h1;
            *(uint4*)(smAL + off)      = l0;
            *(uint4*)(smAL + off + 16) = l1;
            *(uint4*)(smBH + off)      = bh0;
            *(uint4*)(smBH + off + 16) = bh1;
            *(uint4*)(smBL + off)      = bl0;
            *(uint4*)(smBL + off + 16) = bl1;
        }
        __syncthreads();

#pragma unroll
        for (int ks = 0; ks < 2; ks++) {
            const int kb = ks * 16;
            uint32_t bhf[4][2], blf[4][2];
#pragma unroll
            for (int nt = 0; nt < 4; nt++) {
                int row = wn * 32 + nt * 8 + grp;
                int boff = row * RSTRIDE + (kb + tig * 2) * 2;
                bhf[nt][0] = *(uint32_t*)(smBH + boff);
                bhf[nt][1] = *(uint32_t*)(smBH + boff + 16);
                blf[nt][0] = *(uint32_t*)(smBL + boff);
                blf[nt][1] = *(uint32_t*)(smBL + boff + 16);
            }
#pragma unroll
            for (int mt = 0; mt < 4; mt++) {
                int row = wm * 64 + mt * 16 + grp;
                int a0o = row * RSTRIDE + (kb + tig * 2) * 2;
                int a1o = a0o + 8 * RSTRIDE;
                uint32_t ah0 = *(uint32_t*)(smAH + a0o);
                uint32_t ah1 = *(uint32_t*)(smAH + a1o);
                uint32_t ah2 = *(uint32_t*)(smAH + a0o + 16);
                uint32_t ah3 = *(uint32_t*)(smAH + a1o + 16);
                uint32_t al0 = *(uint32_t*)(smAL + a0o);
                uint32_t al1 = *(uint32_t*)(smAL + a1o);
                uint32_t al2 = *(uint32_t*)(smAL + a0o + 16);
                uint32_t al3 = *(uint32_t*)(smAL + a1o + 16);
#pragma unroll
                for (int nt = 0; nt < 4; nt++) {
                    MMA_BF16(acc[mt][nt], ah0, ah1, ah2, ah3, bhf[nt][0], bhf[nt][1]);
                    MMA_BF16(acc[mt][nt], al0, al1, al2, al3, bhf[nt][0], bhf[nt][1]);
                    MMA_BF16(acc[mt][nt], ah0, ah1, ah2, ah3, blf[nt][0], blf[nt][1]);
                }
            }
        }
    }

#pragma unroll
    for (int nt = 0; nt < 4; nt++) {
        int j0 = nBase + wn * 32 + nt * 8 + tig * 2;
        float bb0 = __ldg(&bias[j0]);
        float bb1 = __ldg(&bias[j0 + 1]);
#pragma unroll
        for (int mt = 0; mt < 4; mt++) {
            int m0 = mBase + wm * 64 + mt * 16 + grp;
            st_xwt(m0,     j0,     acc[mt][nt][0] + bb0);
            st_xwt(m0,     j0 + 1, acc[mt][nt][1] + bb1);
            st_xwt(m0 + 8, j0,     acc[mt][nt][2] + bb0);
            st_xwt(m0 + 8, j0 + 1, acc[mt][nt][3] + bb1);
        }
    }
}

// ---------------------------------------------------------------------------
__device__ __forceinline__ float sigf(float x) {
    return 1.0f / (1.0f + __expf(-x));
}
__device__ __forceinline__ float tanhfast(float x) {
    float e = __expf(2.0f * x);
    return 1.0f - 2.0f / (e + 1.0f);
}

// Distributed-flag grid barrier: block writes own flag, block 0 collects + releases.
__device__ __forceinline__ void gbar(unsigned idx, int bu, int tid) {
    __syncthreads();
    if (bu == 0) {
        if (tid > 0 && tid < GRID_R) {
            const unsigned* f = &g_arrive[tid * 8];
            while (ld_acq(f) < idx) __nanosleep(20);
        }
        __syncthreads();
        if (tid == 0) {
            __threadfence();
            st_rel(&g_rel, idx);
        }
        __syncthreads();
    } else {
        if (tid == 0) {
            __threadfence();
            st_rel(&g_arrive[bu * 8], idx);
            while (ld_acq(&g_rel) < idx) __nanosleep(20);
        }
        __syncthreads();
    }
}

// ---------------------------------------------------------------------------
// HMMA persistent scan, flat-load + half overlap.
// Block bu owns 16 gate-unit rows r=ut*4+g (units bu*4..bu*4+3).
// 512 threads = 16 warps: mq = batch tile (16 b), kq = 64-unit k-column pair.
// Warp kq covers units [kq*64, kq*64+64) and [256+kq*64, 256+kq*64+64).
// smem: h hi (64x1040B) | h lo | sD[4][64][20]f32 | csh[256]f32
// ---------------------------------------------------------------------------
#define HROW 1040
#define HBUF (64 * HROW)                    // 66,560
#define SD_OFF (2 * HBUF)                   // 133,120
#define SDS 20
#define CSH_OFF (SD_OFF + 4 * 64 * SDS * 4) // 153,600
#define SMEM_SCAN (CSH_OFF + 1024)          // 154,624

__global__ __launch_bounds__(512, 1) void lstm_scan_kernel(
    const float* __restrict__ c0, const float* __restrict__ h0,
    float* __restrict__ out)
{
    extern __shared__ __align__(16) char sm[];
    float* sD  = (float*)(sm + SD_OFF);
    float* csh = (float*)(sm + CSH_OFF);
    const uint32_t sbase = smem_u32(sm);

    const int bu = blockIdx.x;
    const int u_base = bu * 4;
    const int tid = threadIdx.x;
    const int lane = tid & 31;
    const int wid = tid >> 5;
    const int grp = lane >> 2;
    const int tig = lane & 3;
    const int mq = wid & 3;            // batch tile (16 batches)
    const int kq = wid >> 2;           // k column (64 units per half)
    const int ab = tid >> 2;           // activation batch (tid<256)
    const int au = tid & 3;            // activation unit

    // ---- Wh B fragments -> registers. ks<4: u0=kq*64+ks*16 ; ks>=4: +256 ----
    uint32_t bH[8][2][2], bL[8][2][2];
    {
        const __nv_bfloat16* baseH = g_whB_hi + (size_t)bu * 16 * 512;
        const __nv_bfloat16* baseL = g_whB_lo + (size_t)bu * 16 * 512;
#pragma unroll
        for (int ks = 0; ks < 8; ks++) {
            int u0 = (ks < 4) ? (kq * 64 + ks * 16) : (256 + kq * 64 + (ks - 4) * 16);
            int k = u0 + tig * 2;
#pragma unroll
            for (int nt = 0; nt < 2; nt++) {
                int r = nt * 8 + grp;
                bH[ks][nt][0] = *(const uint32_t*)(baseH + (size_t)r * 512 + k);
                bH[ks][nt][1] = *(const uint32_t*)(baseH + (size_t)r * 512 + k + 8);
                bL[ks][nt][0] = *(const uint32_t*)(baseL + (size_t)r * 512 + k);
                bL[ks][nt][1] = *(const uint32_t*)(baseL + (size_t)r * 512 + k + 8);
            }
        }
    }

    if (tid < 256) {
        csh[tid] = c0[ab * HH + u_base + au];
        float hv = h0[ab * HH + u_base + au];
        __nv_bfloat16 hi = __float2bfloat16(hv);
        __nv_bfloat16 lo = __float2bfloat16(hv - __bfloat162float(hi));
        g_hb_hi[0][ab * HH + u_base + au] = hi;
        g_hb_lo[0][ab * HH + u_base + au] = lo;
    }
    unsigned bidx = 1;
    gbar(bidx++, bu, tid);

    float* ys = out + 2 * BATCH * HH;

    // copy mapping: idx = tid + q*512 over 64 rows x 32 segs per half
    for (int s = 0; s < TT; s++) {
        const int ph = s & 1;

        float4 xw = make_float4(0.f, 0.f, 0.f, 0.f);
        if (tid < 256)
            xw = __ldg((const float4*)g_xwt +
                       ((size_t)(s * 128 + bu) * 64 + ab) * 4 + au);

        const char* hsH = (const char*)g_hb_hi[ph];
        const char* hsL = (const char*)g_hb_lo[ph];

        // half 0 (u<256): rows' first 512B
#pragma unroll
        for (int q = 0; q < 4; q++) {
            int idx = tid + q * 512;
            int row = idx >> 5, sg = (idx & 31) * 16;
            CP_ASYNC16(sbase + row * HROW + sg,        hsH + row * 1024 + sg);
            CP_ASYNC16(sbase + HBUF + row * HROW + sg, hsL + row * 1024 + sg);
        }
        CP_COMMIT();
        // half 1 (u>=256): rows' second 512B
#pragma unroll
        for (int q = 0; q < 4; q++) {
            int idx = tid + q * 512;
            int row = idx >> 5, sg = (idx & 31) * 16;
            CP_ASYNC16(sbase + row * HROW + 512 + sg,        hsH + row * 1024 + 512 + sg);
            CP_ASYNC16(sbase + HBUF + row * HROW + 512 + sg, hsL + row * 1024 + 512 + sg);
        }
        CP_COMMIT();

        float acc[2][4];
#pragma unroll
        for (int nt = 0; nt < 2; nt++)
#pragma unroll
            for (int q = 0; q < 4; q++) acc[nt][q] = 0.f;

        const char* bufH = sm;
        const char* bufL = sm + HBUF;
        const int arow = mq * 16 + grp;

        CP_WAIT(1);            // half 0 landed
        __syncthreads();
#pragma unroll
        for (int ks = 0; ks < 4; ks++) {
            int col = (kq * 64 + ks * 16 + tig * 2) * 2;
            int aoff = arow * HROW + col;
            uint32_t ah0 = *(const uint32_t*)(bufH + aoff);
            uint32_t ah1 = *(const uint32_t*)(bufH + aoff + 8 * HROW);
            uint32_t ah2 = *(const uint32_t*)(bufH + aoff + 16);
            uint32_t ah3 = *(const uint32_t*)(bufH + aoff + 8 * HROW + 16);
            uint32_t al0 = *(const uint32_t*)(bufL + aoff);
            uint32_t al1 = *(const uint32_t*)(bufL + aoff + 8 * HROW);
            uint32_t al2 = *(const uint32_t*)(bufL + aoff + 16);
            uint32_t al3 = *(const uint32_t*)(bufL + aoff + 8 * HROW + 16);
#pragma unroll
            for (int nt = 0; nt < 2; nt++) {
                MMA_BF16(acc[nt], ah0, ah1, ah2, ah3, bH[ks][nt][0], bH[ks][nt][1]);
                MMA_BF16(acc[nt], al0, al1, al2, al3, bH[ks][nt][0], bH[ks][nt][1]);
                MMA_BF16(acc[nt], ah0, ah1, ah2, ah3, bL[ks][nt][0], bL[ks][nt][1]);
            }
        }
        CP_WAIT(0);            // half 1 landed
        __syncthreads();
#pragma unroll
        for (int ks = 4; ks < 8; ks++) {
            int col = (256 + kq * 64 + (ks - 4) * 16 + tig * 2) * 2;
            int aoff = arow * HROW + col;
            uint32_t ah0 = *(const uint32_t*)(bufH + aoff);
            uint32_t ah1 = *(const uint32_t*)(bufH + aoff + 8 * HROW);
            uint32_t ah2 = *(const uint32_t*)(bufH + aoff + 16);
            uint32_t ah3 = *(const uint32_t*)(bufH + aoff + 8 * HROW + 16);
            uint32_t al0 = *(const uint32_t*)(bufL + aoff);
            uint32_t al1 = *(const uint32_t*)(bufL + aoff + 8 * HROW);
            uint32_t al2 = *(const uint32_t*)(bufL + aoff + 16);
            uint32_t al3 = *(const uint32_t*)(bufL + aoff + 8 * HROW + 16);
#pragma unroll
            for (int nt = 0; nt < 2; nt++) {
                MMA_BF16(acc[nt], ah0, ah1, ah2, ah3, bH[ks][nt][0], bH[ks][nt][1]);
                MMA_BF16(acc[nt], al0, al1, al2, al3, bH[ks][nt][0], bH[ks][nt][1]);
                MMA_BF16(acc[nt], ah0, ah1, ah2, ah3, bL[ks][nt][0], bL[ks][nt][1]);
            }
        }

        // store D partials: sD[kq][b][r], row stride SDS
#pragma unroll
        for (int nt = 0; nt < 2; nt++) {
            *(float2*)&sD[(kq * 64 + mq * 16 + grp) * SDS + nt * 8 + tig * 2] =
                make_float2(acc[nt][0], acc[nt][1]);
            *(float2*)&sD[(kq * 64 + mq * 16 + grp + 8) * SDS + nt * 8 + tig * 2] =
                make_float2(acc[nt][2], acc[nt][3]);
        }
        __syncthreads();

        if (tid < 256) {
            float4 s0 = *(float4*)&sD[(0 * 64 + ab) * SDS + au * 4];
            float4 s1 = *(float4*)&sD[(1 * 64 + ab) * SDS + au * 4];
            float4 s2 = *(float4*)&sD[(2 * 64 + ab) * SDS + au * 4];
            float4 s3 = *(float4*)&sD[(3 * 64 + ab) * SDS + au * 4];
            float si = xw.x + s0.x + s1.x + s2.x + s3.x;
            float sf = xw.y + s0.y + s1.y + s2.y + s3.y;
            float sg = xw.z + s0.z + s1.z + s2.z + s3.z;
            float so = xw.w + s0.w + s1.w + s2.w + s3.w;

            float ig = sigf(si);
            float fg = sigf(sf);
            float gg = tanhfast(sg);
            float og = sigf(so);
            float cold = csh[tid];
            float cnew = fg * cold + ig * gg;
            float hnew = og * tanhfast(cnew);
            csh[tid] = cnew;

            __nv_bfloat16 hi = __float2bfloat16(hnew);
            __nv_bfloat16 lo = __float2bfloat16(hnew - __bfloat162float(hi));
            int uo = ab * HH + u_base + au;
            g_hb_hi[ph ^ 1][uo] = hi;
            g_hb_lo[ph ^ 1][uo] = lo;

            ys[((size_t)ab * TT + s) * HH + u_base + au] = hnew;
            if (s == TT - 1) {
                out[ab * HH + u_base + au] = cnew;                 // cT
                out[BATCH * HH + ab * HH + u_base + au] = hnew;    // hT
            }
        }

        if (s < TT - 1) gbar(bidx++, bu, tid);
    }
}

// ---------------------------------------------------------------------------
extern "C" void kernel_launch(void* const* d_in, const int* in_sizes, int n_in,
                              void* d_out, int out_size) {
    const float* x    = (const float*)d_in[0];   // [64][1024][512]
    const float* c0   = (const float*)d_in[1];   // [64][512]
    const float* h0   = (const float*)d_in[2];   // [64][512]
    const float* Wi   = (const float*)d_in[3];   // [512][2048]
    const float* Wh   = (const float*)d_in[4];   // [512][2048]
    const float* bias = (const float*)d_in[5];   // [2048]
    float* out = (float*)d_out;                  // cT | hT | ys

    cudaFuncSetAttribute(lstm_scan_kernel,
                         cudaFuncAttributeMaxDynamicSharedMemorySize, SMEM_SCAN);

    pack_wi_kernel<<<4096, 256>>>(Wi);
    pack_whB_kernel<<<4096, 256>>>(Wh);
    reset_bar_kernel<<<1, 1024>>>();
    gemm_hmma_kernel<<<dim3(16, 512), 256>>>(x, bias);
    lstm_scan_kernel<<<GRID_R, 512, SMEM_SCAN>>>(c0, h0, out);
}